// round 17
// baseline (speedup 1.0000x reference)
#include <cuda_runtime.h>
#include <cooperative_groups.h>
#include <math.h>
#include <stdint.h>

namespace cg = cooperative_groups;

// ---------------------------------------------------------------------------
// ElectricOverflow. Grid 512x512x8 (8MB, L2-resident), padded both sides.
//
// Single cooperative persistent kernel: zero -> grid.sync -> scatter ->
// grid.sync -> reduce. Removes two launch/drain boundaries (PDL only
// partially hid them); phases run on a perfectly-sized resident grid.
//
// Scatter emission = champion (R4): z-border cull (reference overwrites all
// border bins with 1.0 -> those atomics are dead), x/y out-of-range lanes
// alias into padding (never read), sector-local red2 pairing (never crosses
// the 32B z-row sector). Scatter itself is at the LTS fp32-atomic service
// floor (~17us; 7 variants neutral).
// ---------------------------------------------------------------------------

#define NM_ 250000
#define NT_ 8000
#define NF_ 60000
#define N_  (NM_ + NT_ + NF_)    // 318000
#define NX_ 512
#define NY_ 512
#define NZ_ 8
#define NBINS_ (NX_ * NY_ * NZ_) // 2097152
#define PADF_ 4424               // covers ix/iy in [-1,512], z in [1,6]

#define SQRT2H 0.7071067811865476f
#define C1 0.41421356237309515f  // sqrt2 - 1
#define C2 0.5857864376269049f   // 2 - sqrt2

__device__ __align__(128) float g_pad[PADF_ + NBINS_ + PADF_];
#define GRID_B (g_pad + PADF_)

__device__ __forceinline__ void red1(float* p, float v) {
    asm volatile("red.global.add.f32 [%0], %1;" :: "l"(p), "f"(v) : "memory");
}
__device__ __forceinline__ void red2(float* p, float a, float b) {
    asm volatile("red.global.add.v2.f32 [%0], {%1, %2};"
                 :: "l"(p), "f"(a), "f"(b) : "memory");
}

// Emit up to 3 z-lane REDs, pairing adjacent surviving lanes when 8B-aligned.
// Never crosses the 32B z-row sector.
__device__ __forceinline__ void emit_z(float* p, float wxy,
                                       float v0, float v1, float v2,
                                       bool e0, bool e1, bool e2, bool even0) {
    if (e0 && e1 && even0) {
        red2(p, wxy * v0, wxy * v1);
        if (e2) red1(p + 2, wxy * v2);
    } else {
        if (e0) red1(p, wxy * v0);
        if (e1 && e2 && !even0) red2(p + 1, wxy * v1, wxy * v2);
        else {
            if (e1) red1(p + 1, wxy * v1);
            if (e2) red1(p + 2, wxy * v2);
        }
    }
}

// Champion scatter body for one node index n (0..N_-1).
__device__ __forceinline__ void scatter_one(int n,
                                            const float* __restrict__ pos,
                                            const float* __restrict__ nsx,
                                            const float* __restrict__ nsy,
                                            const float* __restrict__ nsz) {
    bool isFill = (n >= NM_ + NF_);
    int j = isFill ? (n - NF_) : ((n < NM_) ? n : (n + NT_));

    float sx = nsx[j], sy = nsy[j], sz = nsz[j];
    float px = pos[j], py = pos[N_ + j], pz = pos[2 * N_ + j];

    if (!isFill) {
        const float w = sx * sy * sz * 0.35355339059327373f;  // /(2*sqrt2)
        float x0 = px + 0.5f * sx - SQRT2H;
        float y0 = py + 0.5f * sy - SQRT2H;
        float z0 = pz + 0.5f * sz - SQRT2H;

        float fxf = floorf(x0), fyf = floorf(y0), fzf = floorf(z0);
        int ix0 = (int)fxf, iy0 = (int)fyf, iz0 = (int)fzf;
        float fx = x0 - fxf, fy = y0 - fyf, fz = z0 - fzf;

        float ox[3] = { 1.0f - fx, fminf(fx + C1, 1.0f), fmaxf(fx - C2, 0.0f) };
        float oy[3] = { 1.0f - fy, fminf(fy + C1, 1.0f), fmaxf(fy - C2, 0.0f) };

        float v0 = 1.0f - fz;
        float v1 = fminf(fz + C1, 1.0f);
        float v2 = fmaxf(fz - C2, 0.0f);
        bool e0 = (iz0 >= 1) & (iz0 <= 6);
        bool e1 = (iz0 >= 0) & (iz0 <= 5);
        bool e2 = (iz0 >= -1) & (iz0 <= 4) & (v2 > 0.0f);
        if (!(e0 | e1 | e2)) return;
        bool even0 = ((iz0 & 1) == 0);

#pragma unroll
        for (int a = 0; a < 3; ++a) {
            if (ox[a] == 0.0f) continue;          // only a==2 can be 0
            float wx = w * ox[a];
#pragma unroll
            for (int b = 0; b < 3; ++b) {
                if (oy[b] == 0.0f) continue;
                float* p = GRID_B + (((ix0 + a) * NY_ + (iy0 + b)) << 3) + iz0;
                emit_z(p, wx * oy[b], v0, v1, v2, e0, e1, e2, even0);
            }
        }
    } else {
        float fxf = floorf(px), fyf = floorf(py), fzf = floorf(pz);
        int ix0 = (int)fxf, iy0 = (int)fyf, iz0 = (int)fzf;  // iz0 in [0,6]
        float fx = px - fxf, fy = py - fyf, fz = pz - fzf;

        float ox[2] = { fminf(1.0f - fx, sx), fmaxf(fx + sx - 1.0f, 0.0f) };
        float oy[2] = { fminf(1.0f - fy, sy), fmaxf(fy + sy - 1.0f, 0.0f) };
        float v0 = fminf(1.0f - fz, sz);
        float v1 = fmaxf(fz + sz - 1.0f, 0.0f);
        bool e0 = (iz0 >= 1);
        bool e1 = (iz0 <= 5) & (v1 > 0.0f);
        if (!(e0 | e1)) return;
        bool even0 = ((iz0 & 1) == 0);

#pragma unroll
        for (int a = 0; a < 2; ++a) {
            if (ox[a] == 0.0f) continue;
#pragma unroll
            for (int b = 0; b < 2; ++b) {
                if (oy[b] == 0.0f) continue;
                float wxy = ox[a] * oy[b];
                float* p = GRID_B + (((ix0 + a) * NY_ + (iy0 + b)) << 3) + iz0;
                if (e0 && e1 && even0) red2(p, wxy * v0, wxy * v1);
                else {
                    if (e0) red1(p, wxy * v0);
                    if (e1) red1(p + 1, wxy * v1);
                }
            }
        }
    }
}

// ---------------------------------------------------------------------------
// Fused cooperative kernel: zero | sync | scatter | sync | reduce.
// ---------------------------------------------------------------------------
__global__ void __launch_bounds__(256, 8)
k_fused(const float* __restrict__ pos,
        const float* __restrict__ nsx,
        const float* __restrict__ nsy,
        const float* __restrict__ nsz,
        float* __restrict__ out) {
    cg::grid_group g = cg::this_grid();
    const int T = gridDim.x * blockDim.x;
    const int t = blockIdx.x * blockDim.x + threadIdx.x;

    // ---- phase 1: zero the grid (grid-stride float4) ----
    {
        float4* g4 = reinterpret_cast<float4*>(GRID_B);
        const float4 z = make_float4(0.f, 0.f, 0.f, 0.f);
        for (int i = t; i < NBINS_ / 4; i += T) g4[i] = z;
        if (t == 0) { out[0] = 0.0f; out[1] = 1.0f; }  // border density = 1.0
    }
    g.sync();

    // ---- phase 2: scatter (grid-stride over nodes) ----
    for (int n = t; n < N_; n += T)
        scatter_one(n, pos, nsx, nsy, nsz);
    g.sync();

    // ---- phase 3: reduce (grid-stride over (x,y) z-rows) ----
    float s = 0.0f, m = 0.0f;
    for (int r = t; r < NX_ * NY_; r += T) {
        int ix = r >> 9;
        int iy = r & 511;
        if (ix >= 1 && ix <= NX_ - 2 && iy >= 1 && iy <= NY_ - 2) {
            const float4* g4 = reinterpret_cast<const float4*>(GRID_B) + r * 2;
            float4 a = g4[0];
            float4 b = g4[1];
            s += fmaxf(a.y - 1.0f, 0.0f) + fmaxf(a.z - 1.0f, 0.0f) +
                 fmaxf(a.w - 1.0f, 0.0f) + fmaxf(b.x - 1.0f, 0.0f) +
                 fmaxf(b.y - 1.0f, 0.0f) + fmaxf(b.z - 1.0f, 0.0f);
            m = fmaxf(m, fmaxf(fmaxf(fmaxf(a.y, a.z), fmaxf(a.w, b.x)),
                               fmaxf(b.y, b.z)));
        }
    }
#pragma unroll
    for (int o = 16; o > 0; o >>= 1) {
        s += __shfl_down_sync(0xffffffffu, s, o);
        m = fmaxf(m, __shfl_down_sync(0xffffffffu, m, o));
    }
    __shared__ float ss[8], sm[8];
    int lane = threadIdx.x & 31;
    int wid = threadIdx.x >> 5;
    if (lane == 0) { ss[wid] = s; sm[wid] = m; }
    __syncthreads();
    if (wid == 0) {
        int nw = blockDim.x >> 5;
        s = (lane < nw) ? ss[lane] : 0.0f;
        m = (lane < nw) ? sm[lane] : 0.0f;
#pragma unroll
        for (int o = 4; o > 0; o >>= 1) {
            s += __shfl_down_sync(0xffffffffu, s, o);
            m = fmaxf(m, __shfl_down_sync(0xffffffffu, m, o));
        }
        if (lane == 0) {
            atomicAdd(&out[0], s);
            atomicMax(reinterpret_cast<int*>(&out[1]), __float_as_int(m));
        }
    }
}

extern "C" void kernel_launch(void* const* d_in, const int* in_sizes, int n_in,
                              void* d_out, int out_size) {
    const float* pos = (const float*)d_in[0];
    const float* nsx = (const float*)d_in[1];
    const float* nsy = (const float*)d_in[2];
    const float* nsz = (const float*)d_in[3];
    float* out = (float*)d_out;

    // Capture-safe queries (no allocation, no sync).
    static int gridBlocks = 0;   // computed once; deterministic per device
    if (gridBlocks == 0) {
        int dev = 0;
        cudaGetDevice(&dev);
        int numSMs = 0;
        cudaDeviceGetAttribute(&numSMs, cudaDevAttrMultiProcessorCount, dev);
        int maxPerSM = 0;
        cudaOccupancyMaxActiveBlocksPerMultiprocessor(&maxPerSM, k_fused, 256, 0);
        if (maxPerSM < 1) maxPerSM = 1;
        gridBlocks = numSMs * maxPerSM;
    }

    void* args[] = { (void*)&pos, (void*)&nsx, (void*)&nsy, (void*)&nsz,
                     (void*)&out };
    cudaLaunchCooperativeKernel((void*)k_fused, dim3(gridBlocks), dim3(256),
                                args, 0, (cudaStream_t)0);
}